// round 10
// baseline (speedup 1.0000x reference)
#include <cuda_runtime.h>
#include <cuda_fp16.h>
#include <float.h>

// ---------------------------------------------------------------------------
// GAT 2-layer forward, GB300 (sm_103a).  R4 design (6th resubmit, infra):
//  - SGEMM: f32x2 FMA with pre-duplicated A operands in smem (no per-FMA pack)
//  - h1/h2 stored fp16 (gather-only consumers), fp32 accumulation
//  - CSR: rank captured in hist (atomic-free scatter)
//  - fused attention epilogue + global-shift single-pass softmax (from R3)
// ---------------------------------------------------------------------------

#define NMAX 50048
#define EMAX 800000
#define EPMAX (EMAX + NMAX)

typedef unsigned long long u64;

__device__ int      g_deg[NMAX];
__device__ int      g_rowptr[NMAX + 1];
__device__ int      g_col[EPMAX];
__device__ int      g_rank[EMAX];
__device__ __align__(16) __half g_h1h[(size_t)NMAX * 128];
__device__ __align__(16) __half g_h2h[(size_t)NMAX * 64];
__device__ __align__(16) float  g_out1[(size_t)NMAX * 128];
__device__ float    g_as1[NMAX * 4];
__device__ float    g_ad1[NMAX * 4];
__device__ float    g_as2[NMAX];
__device__ float    g_ad2[NMAX];
__device__ unsigned g_Mu[8];

// ---- helpers ---------------------------------------------------------------

__device__ __forceinline__ u64 pack2(float lo, float hi) {
    u64 r; asm("mov.b64 %0, {%1, %2};" : "=l"(r) : "f"(lo), "f"(hi)); return r;
}
__device__ __forceinline__ u64 fma2(u64 a, u64 b, u64 c) {
    u64 d; asm("fma.rn.f32x2 %0, %1, %2, %3;" : "=l"(d) : "l"(a), "l"(b), "l"(c)); return d;
}
__device__ __forceinline__ float2 unpack2(u64 v) {
    float lo, hi; asm("mov.b64 {%0, %1}, %2;" : "=f"(lo), "=f"(hi) : "l"(v));
    return make_float2(lo, hi);
}
__device__ __forceinline__ unsigned encf(float f) {
    unsigned b = __float_as_uint(f);
    return (b & 0x80000000u) ? ~b : (b | 0x80000000u);
}
__device__ __forceinline__ float decf(unsigned u) {
    return __uint_as_float((u & 0x80000000u) ? (u ^ 0x80000000u) : ~u);
}

// ---------------------------------------------------------------------------
// CSR construction
// ---------------------------------------------------------------------------

__global__ void zero_kernel(int N) {
    int i = blockIdx.x * blockDim.x + threadIdx.x;
    if (i < N) g_deg[i] = 1;          // slot 0 reserved for the self loop
    if (i < 8) g_Mu[i] = 0u;
}

// histogram + per-edge rank (slot within destination segment)
__global__ void hist_kernel(const int* __restrict__ ei, int E) {
    int i = blockIdx.x * blockDim.x + threadIdx.x;
    int base = i * 4;
    if (base >= E) return;
    if (base + 3 < E) {
        int4 d4 = *(const int4*)&ei[E + base];
        int4 r4;
        r4.x = atomicAdd(&g_deg[d4.x], 1);
        r4.y = atomicAdd(&g_deg[d4.y], 1);
        r4.z = atomicAdd(&g_deg[d4.z], 1);
        r4.w = atomicAdd(&g_deg[d4.w], 1);
        *(int4*)&g_rank[base] = r4;
    } else {
        for (int k = base; k < E; k++)
            g_rank[k] = atomicAdd(&g_deg[ei[E + k]], 1);
    }
}

// single block, smem-staged exclusive scan of g_deg -> g_rowptr
__global__ void scan_kernel(int N) {
    extern __shared__ int sm[];
    int* sdeg = sm;
    int* ssum = sm + N;
    int* soff = sm + N + 1024;
    int t = threadIdx.x;
    int chunk = (N + 1023) / 1024;

    for (int i = t; i < N; i += 1024) sdeg[i] = g_deg[i];
    __syncthreads();

    int c0 = t * chunk;
    int c1 = min(c0 + chunk, N);
    int run = 0;
    for (int i = c0; i < c1; i++) { int v = sdeg[i]; sdeg[i] = run; run += v; }
    ssum[t] = run;
    __syncthreads();
    for (int off = 1; off < 1024; off <<= 1) {
        int v = (t >= off) ? ssum[t - off] : 0;
        __syncthreads();
        ssum[t] += v;
        __syncthreads();
    }
    soff[t] = ssum[t] - run;
    __syncthreads();

    for (int i = t; i < N; i += 1024)
        g_rowptr[i] = sdeg[i] + soff[i / chunk];
    if (t == 1023) g_rowptr[N] = ssum[1023];
}

// atomic-free scatter: slot = rowptr[dst] + rank
__global__ void scatter_kernel(const int* __restrict__ ei, int E, int N) {
    int EV = (E + 3) / 4;
    int i = blockIdx.x * blockDim.x + threadIdx.x;
    if (i < EV) {
        int base = i * 4;
        if (base + 3 < E) {
            int4 s4 = *(const int4*)&ei[base];
            int4 d4 = *(const int4*)&ei[E + base];
            int4 r4 = *(const int4*)&g_rank[base];
            g_col[g_rowptr[d4.x] + r4.x] = s4.x;
            g_col[g_rowptr[d4.y] + r4.y] = s4.y;
            g_col[g_rowptr[d4.z] + r4.z] = s4.z;
            g_col[g_rowptr[d4.w] + r4.w] = s4.w;
        } else {
            for (int k = base; k < E; k++)
                g_col[g_rowptr[ei[E + k]] + g_rank[k]] = ei[k];
        }
    } else if (i - EV < N) {
        int node = i - EV;
        g_col[g_rowptr[node]] = node;   // self loop, slot 0
    }
}

// ---------------------------------------------------------------------------
// SGEMM (fp32 in, fp16 out) + fused attention epilogue.
// As2 smem tile holds each A value pre-duplicated as f32x2 pairs.
// ---------------------------------------------------------------------------

template <int NCOLS, int H>
__global__ __launch_bounds__(256)
void sgemm_attn_kernel(const float* __restrict__ A, const float* __restrict__ W,
                       __half* __restrict__ C, const float* __restrict__ att_s,
                       const float* __restrict__ att_d,
                       float* __restrict__ a_s, float* __restrict__ a_d,
                       int mu0, int M) {
    constexpr int KD = 128, KC = 32, MT = 64;
    constexpr int CG  = NCOLS / 4;
    constexpr int RPT = MT * CG / 256;
    constexpr int CH  = NCOLS / H;
    constexpr int LPG = CH / 4;
    constexpr int MP  = MT + 2;              // plane stride 66*8B (16B multiple)

    __shared__ u64   As2[KC][MP];            // duplicated f32x2 pairs
    __shared__ float Ws[KC][NCOLS];
    __shared__ unsigned sm_mx[H];

    int tid = threadIdx.x;
    int cg  = tid % CG;
    int rg  = tid / CG;
    int row0 = blockIdx.x * MT;
    if (tid < H) sm_mx[tid] = 0u;

    u64 acc[RPT][2];
#pragma unroll
    for (int r = 0; r < RPT; r++) { acc[r][0] = 0ull; acc[r][1] = 0ull; }

    for (int kc = 0; kc < KD; kc += KC) {
        for (int i = tid; i < MT * KC / 4; i += 256) {
            int r  = i / (KC / 4);
            int c4 = i % (KC / 4);
            float4 v = make_float4(0.f, 0.f, 0.f, 0.f);
            if (row0 + r < M)
                v = *(const float4*)&A[(size_t)(row0 + r) * KD + kc + c4 * 4];
            As2[c4 * 4 + 0][r] = pack2(v.x, v.x);
            As2[c4 * 4 + 1][r] = pack2(v.y, v.y);
            As2[c4 * 4 + 2][r] = pack2(v.z, v.z);
            As2[c4 * 4 + 3][r] = pack2(v.w, v.w);
        }
        for (int i = tid; i < KC * NCOLS / 4; i += 256) {
            int r  = i / (NCOLS / 4);
            int c4 = i % (NCOLS / 4);
            *(float4*)&Ws[r][c4 * 4] = *(const float4*)&W[(size_t)(kc + r) * NCOLS + c4 * 4];
        }
        __syncthreads();
#pragma unroll 4
        for (int k = 0; k < KC; k++) {
            const u64* wp = reinterpret_cast<const u64*>(&Ws[k][cg * 4]);
            u64 w01 = wp[0], w23 = wp[1];
            u64 av[RPT];
            const ulonglong2* ap = reinterpret_cast<const ulonglong2*>(&As2[k][rg * RPT]);
#pragma unroll
            for (int p = 0; p < RPT / 2; p++) {
                ulonglong2 a2 = ap[p];
                av[p * 2 + 0] = a2.x;
                av[p * 2 + 1] = a2.y;
            }
#pragma unroll
            for (int r = 0; r < RPT; r++) {
                acc[r][0] = fma2(av[r], w01, acc[r][0]);
                acc[r][1] = fma2(av[r], w23, acc[r][1]);
            }
        }
        __syncthreads();
    }

    int col = cg * 4;
    float w_s0 = __ldg(&att_s[col]),     w_s1 = __ldg(&att_s[col + 1]);
    float w_s2 = __ldg(&att_s[col + 2]), w_s3 = __ldg(&att_s[col + 3]);
    float w_d0 = __ldg(&att_d[col]),     w_d1 = __ldg(&att_d[col + 1]);
    float w_d2 = __ldg(&att_d[col + 2]), w_d3 = __ldg(&att_d[col + 3]);

#pragma unroll
    for (int r = 0; r < RPT; r++) {
        int row = row0 + rg * RPT + r;
        float2 c01 = unpack2(acc[r][0]);
        float2 c23 = unpack2(acc[r][1]);
        if (row < M) {
            __half2 hlo = __float22half2_rn(c01);
            __half2 hhi = __float22half2_rn(c23);
            uint2 u;
            u.x = *reinterpret_cast<unsigned*>(&hlo);
            u.y = *reinterpret_cast<unsigned*>(&hhi);
            *(uint2*)&C[(size_t)row * NCOLS + col] = u;
        }
        float ps = c01.x * w_s0 + c01.y * w_s1 + c23.x * w_s2 + c23.y * w_s3;
        float pd = c01.x * w_d0 + c01.y * w_d1 + c23.x * w_d2 + c23.y * w_d3;
#pragma unroll
        for (int off = LPG / 2; off > 0; off >>= 1) {
            ps += __shfl_xor_sync(0xffffffffu, ps, off);
            pd += __shfl_xor_sync(0xffffffffu, pd, off);
        }
        if ((cg % LPG) == 0 && row < M) {
            int h = cg / LPG;
            a_s[row * H + h] = ps;
            a_d[row * H + h] = pd;
            atomicMax(&sm_mx[h], encf(ps));
        }
    }
    __syncthreads();
    if (tid < H) atomicMax(&g_Mu[mu0 + tid], sm_mx[tid]);
}

// ---------------------------------------------------------------------------
// Single-pass softmax aggregation over fp16 features, fp32 accumulate.
// One warp per destination node; lane owns VECH consecutive channels.
// ---------------------------------------------------------------------------

template <int H, int C, int VECH, bool ELU_OUT>
__global__ void agg_kernel(const __half* __restrict__ hin,
                           const float* __restrict__ a_s,
                           const float* __restrict__ a_dv,
                           const float* __restrict__ bias,
                           float* __restrict__ out, int mu0, int N) {
    constexpr int F = H * C;
    int gw   = (blockIdx.x * blockDim.x + threadIdx.x) >> 5;
    int lane = threadIdx.x & 31;
    if (gw >= N) return;

    int   h_own = (lane * VECH) / C;
    float ad    = __ldg(&a_dv[gw * H + h_own]);
    float tM    = decf(g_Mu[mu0 + h_own]) + ad;
    float S     = fmaxf(tM, 0.2f * tM);

    int beg = g_rowptr[gw], end = g_rowptr[gw + 1];
    float d = 0.f;
    float acc[VECH];
#pragma unroll
    for (int q = 0; q < VECH; q++) acc[q] = 0.f;

    for (int base = beg; base < end; base += 32) {
        int idx = base + lane;
        int sl  = (idx < end) ? g_col[idx] : 0;
        int cnt = min(32, end - base);
#pragma unroll 4
        for (int j = 0; j < cnt; j++) {
            int s = __shfl_sync(0xffffffffu, sl, j);
            float e = __ldg(&a_s[s * H + h_own]) + ad;
            e = fmaxf(e, 0.2f * e);
            float ev = __expf(e - S);
            d += ev;
            const __half* hr = hin + (size_t)s * F + lane * VECH;
            if (VECH == 4) {
                uint2 u = __ldg((const uint2*)hr);
                float2 f0 = __half22float2(*reinterpret_cast<__half2*>(&u.x));
                float2 f1 = __half22float2(*reinterpret_cast<__half2*>(&u.y));
                acc[0] = fmaf(ev, f0.x, acc[0]);
                acc[1] = fmaf(ev, f0.y, acc[1]);
                acc[2] = fmaf(ev, f1.x, acc[2]);
                acc[3] = fmaf(ev, f1.y, acc[3]);
            } else {
                unsigned u = __ldg((const unsigned*)hr);
                float2 f0 = __half22float2(*reinterpret_cast<__half2*>(&u));
                acc[0] = fmaf(ev, f0.x, acc[0]);
                acc[1] = fmaf(ev, f0.y, acc[1]);
            }
        }
    }

    float inv = 1.f / d;
#pragma unroll
    for (int q = 0; q < VECH; q++) {
        int f = lane * VECH + q;
        float v = acc[q] * inv + __ldg(&bias[f]);
        if (ELU_OUT) v = (v > 0.f) ? v : (__expf(v) - 1.f);
        out[(size_t)gw * F + f] = v;
    }
}

// ---------------------------------------------------------------------------
// Launch
// ---------------------------------------------------------------------------

extern "C" void kernel_launch(void* const* d_in, const int* in_sizes, int n_in,
                              void* d_out, int out_size) {
    const float* x    = (const float*)d_in[0];
    const int*   ei   = (const int*)d_in[1];   // int32 [2, E]
    const float* W1   = (const float*)d_in[2];
    const float* as1w = (const float*)d_in[3];
    const float* ad1w = (const float*)d_in[4];
    const float* b1   = (const float*)d_in[5];
    const float* W2   = (const float*)d_in[6];
    const float* as2w = (const float*)d_in[7];
    const float* ad2w = (const float*)d_in[8];
    const float* b2   = (const float*)d_in[9];
    float* out = (float*)d_out;

    int N  = in_sizes[0] / 128;
    int E  = in_sizes[1] / 2;

    void *p_h1, *p_h2, *p_out1, *p_as1, *p_ad1, *p_as2, *p_ad2;
    cudaGetSymbolAddress(&p_h1,   g_h1h);
    cudaGetSymbolAddress(&p_h2,   g_h2h);
    cudaGetSymbolAddress(&p_out1, g_out1);
    cudaGetSymbolAddress(&p_as1,  g_as1);
    cudaGetSymbolAddress(&p_ad1,  g_ad1);
    cudaGetSymbolAddress(&p_as2,  g_as2);
    cudaGetSymbolAddress(&p_ad2,  g_ad2);

    int scanSmem = (N + 2048) * (int)sizeof(int);
    cudaFuncSetAttribute(scan_kernel, cudaFuncAttributeMaxDynamicSharedMemorySize, scanSmem);

    int nodeBlocks = (N + 255) / 256;
    int histBlocks = ((E + 3) / 4 + 255) / 256;
    int scatBlocks = ((E + 3) / 4 + N + 255) / 256;
    int warpBlocks = (N + 7) / 8;
    int gemmBlocks = (N + 63) / 64;

    zero_kernel<<<nodeBlocks, 256>>>(N);
    hist_kernel<<<histBlocks, 256>>>(ei, E);
    scan_kernel<<<1, 1024, scanSmem>>>(N);
    scatter_kernel<<<scatBlocks, 256>>>(ei, E, N);

    sgemm_attn_kernel<128, 4><<<gemmBlocks, 256>>>(
        x, W1, (__half*)p_h1, as1w, ad1w, (float*)p_as1, (float*)p_ad1, 0, N);
    agg_kernel<4, 32, 4, true><<<warpBlocks, 256>>>(
        (const __half*)p_h1, (const float*)p_as1, (const float*)p_ad1,
        b1, (float*)p_out1, 0, N);

    sgemm_attn_kernel<64, 1><<<gemmBlocks, 256>>>(
        (const float*)p_out1, W2, (__half*)p_h2, as2w, ad2w,
        (float*)p_as2, (float*)p_ad2, 4, N);
    agg_kernel<1, 64, 2, false><<<warpBlocks, 256>>>(
        (const __half*)p_h2, (const float*)p_as2, (const float*)p_ad2,
        b2, out, 4, N);
}

// round 14
// speedup vs baseline: 1.1553x; 1.1553x over previous
#include <cuda_runtime.h>
#include <cuda_fp16.h>
#include <float.h>

// ---------------------------------------------------------------------------
// GAT 2-layer forward, GB300 (sm_103a).  R11 (3rd resubmit, infra timeout):
//  - SGEMM: row-paired f32x2 accumulators; A pairs read directly as u64
//    (zero packing MOVs for A), W duplicated via 4 MOV64/k. fp16 C output.
//  - h1/h2 fp16 (gather-only), fp32 accumulate (measured rel_err 1.7e-4)
//  - CSR: rank-from-hist, atomic-free scatter (measured 12.8us)
//  - fused attention epilogue + global-shift single-pass softmax
// ---------------------------------------------------------------------------

#define NMAX 50048
#define EMAX 800000
#define EPMAX (EMAX + NMAX)

typedef unsigned long long u64;

__device__ int      g_deg[NMAX];
__device__ int      g_rowptr[NMAX + 1];
__device__ int      g_col[EPMAX];
__device__ int      g_rank[EMAX];
__device__ __align__(16) __half g_h1h[(size_t)NMAX * 128];
__device__ __align__(16) __half g_h2h[(size_t)NMAX * 64];
__device__ __align__(16) float  g_out1[(size_t)NMAX * 128];
__device__ float    g_as1[NMAX * 4];
__device__ float    g_ad1[NMAX * 4];
__device__ float    g_as2[NMAX];
__device__ float    g_ad2[NMAX];
__device__ unsigned g_Mu[8];

// ---- helpers ---------------------------------------------------------------

__device__ __forceinline__ u64 pack2(float lo, float hi) {
    u64 r; asm("mov.b64 %0, {%1, %2};" : "=l"(r) : "f"(lo), "f"(hi)); return r;
}
__device__ __forceinline__ u64 fma2(u64 a, u64 b, u64 c) {
    u64 d; asm("fma.rn.f32x2 %0, %1, %2, %3;" : "=l"(d) : "l"(a), "l"(b), "l"(c)); return d;
}
__device__ __forceinline__ float2 unpack2(u64 v) {
    float lo, hi; asm("mov.b64 {%0, %1}, %2;" : "=f"(lo), "=f"(hi) : "l"(v));
    return make_float2(lo, hi);
}
__device__ __forceinline__ unsigned encf(float f) {
    unsigned b = __float_as_uint(f);
    return (b & 0x80000000u) ? ~b : (b | 0x80000000u);
}
__device__ __forceinline__ float decf(unsigned u) {
    return __uint_as_float((u & 0x80000000u) ? (u ^ 0x80000000u) : ~u);
}

// ---------------------------------------------------------------------------
// CSR construction
// ---------------------------------------------------------------------------

__global__ void zero_kernel(int N) {
    int i = blockIdx.x * blockDim.x + threadIdx.x;
    if (i < N) g_deg[i] = 1;          // slot 0 reserved for the self loop
    if (i < 8) g_Mu[i] = 0u;
}

__global__ void hist_kernel(const int* __restrict__ ei, int E) {
    int i = blockIdx.x * blockDim.x + threadIdx.x;
    int base = i * 4;
    if (base >= E) return;
    if (base + 3 < E) {
        int4 d4 = *(const int4*)&ei[E + base];
        int4 r4;
        r4.x = atomicAdd(&g_deg[d4.x], 1);
        r4.y = atomicAdd(&g_deg[d4.y], 1);
        r4.z = atomicAdd(&g_deg[d4.z], 1);
        r4.w = atomicAdd(&g_deg[d4.w], 1);
        *(int4*)&g_rank[base] = r4;
    } else {
        for (int k = base; k < E; k++)
            g_rank[k] = atomicAdd(&g_deg[ei[E + k]], 1);
    }
}

__global__ void scan_kernel(int N) {
    extern __shared__ int sm[];
    int* sdeg = sm;
    int* ssum = sm + N;
    int* soff = sm + N + 1024;
    int t = threadIdx.x;
    int chunk = (N + 1023) / 1024;

    for (int i = t; i < N; i += 1024) sdeg[i] = g_deg[i];
    __syncthreads();

    int c0 = t * chunk;
    int c1 = min(c0 + chunk, N);
    int run = 0;
    for (int i = c0; i < c1; i++) { int v = sdeg[i]; sdeg[i] = run; run += v; }
    ssum[t] = run;
    __syncthreads();
    for (int off = 1; off < 1024; off <<= 1) {
        int v = (t >= off) ? ssum[t - off] : 0;
        __syncthreads();
        ssum[t] += v;
        __syncthreads();
    }
    soff[t] = ssum[t] - run;
    __syncthreads();

    for (int i = t; i < N; i += 1024)
        g_rowptr[i] = sdeg[i] + soff[i / chunk];
    if (t == 1023) g_rowptr[N] = ssum[1023];
}

__global__ void scatter_kernel(const int* __restrict__ ei, int E, int N) {
    int EV = (E + 3) / 4;
    int i = blockIdx.x * blockDim.x + threadIdx.x;
    if (i < EV) {
        int base = i * 4;
        if (base + 3 < E) {
            int4 s4 = *(const int4*)&ei[base];
            int4 d4 = *(const int4*)&ei[E + base];
            int4 r4 = *(const int4*)&g_rank[base];
            g_col[g_rowptr[d4.x] + r4.x] = s4.x;
            g_col[g_rowptr[d4.y] + r4.y] = s4.y;
            g_col[g_rowptr[d4.z] + r4.z] = s4.z;
            g_col[g_rowptr[d4.w] + r4.w] = s4.w;
        } else {
            for (int k = base; k < E; k++)
                g_col[g_rowptr[ei[E + k]] + g_rank[k]] = ei[k];
        }
    } else if (i - EV < N) {
        int node = i - EV;
        g_col[g_rowptr[node]] = node;   // self loop, slot 0
    }
}

// ---------------------------------------------------------------------------
// SGEMM (fp32 in, fp16 out) + fused attention epilogue.
// Row-paired f32x2: acc[p][c] holds (row 2p, row 2p+1) for column c.
// A pairs read directly from the transposed smem tile as u64 (no MOV);
// only W is duplicated (4 MOV64 per k).
// ---------------------------------------------------------------------------

template <int NCOLS, int H>
__global__ __launch_bounds__(256)
void sgemm_attn_kernel(const float* __restrict__ A, const float* __restrict__ W,
                       __half* __restrict__ C, const float* __restrict__ att_s,
                       const float* __restrict__ att_d,
                       float* __restrict__ a_s, float* __restrict__ a_d,
                       int mu0, int M) {
    constexpr int KD = 128, KC = 32, MT = 64;
    constexpr int CG  = NCOLS / 4;           // threads across columns
    constexpr int RPT = MT * CG / 256;       // rows per thread (8 or 4)
    constexpr int NP  = RPT / 2;             // row pairs per thread (4 or 2)
    constexpr int CH  = NCOLS / H;
    constexpr int LPG = CH / 4;              // lanes per head group
    constexpr int MP  = MT + 4;              // 68 floats = 272B (16B multiple)

    __shared__ __align__(16) float As[KC][MP];   // transposed A tile
    __shared__ __align__(16) float Ws[KC][NCOLS];
    __shared__ unsigned sm_mx[H];

    int tid = threadIdx.x;
    int cg  = tid % CG;
    int rg  = tid / CG;
    int row0 = blockIdx.x * MT;
    if (tid < H) sm_mx[tid] = 0u;

    u64 acc[NP][4];
#pragma unroll
    for (int p = 0; p < NP; p++)
#pragma unroll
        for (int c = 0; c < 4; c++) acc[p][c] = 0ull;

    for (int kc = 0; kc < KD; kc += KC) {
        // A tile transposed: As[k][row]
        for (int i = tid; i < MT * KC / 4; i += 256) {
            int r  = i / (KC / 4);
            int c4 = i % (KC / 4);
            float4 v = make_float4(0.f, 0.f, 0.f, 0.f);
            if (row0 + r < M)
                v = *(const float4*)&A[(size_t)(row0 + r) * KD + kc + c4 * 4];
            As[c4 * 4 + 0][r] = v.x;
            As[c4 * 4 + 1][r] = v.y;
            As[c4 * 4 + 2][r] = v.z;
            As[c4 * 4 + 3][r] = v.w;
        }
        // W tile (dense fp32)
        for (int i = tid; i < KC * NCOLS / 4; i += 256) {
            int r  = i / (NCOLS / 4);
            int c4 = i % (NCOLS / 4);
            *(float4*)&Ws[r][c4 * 4] = *(const float4*)&W[(size_t)(kc + r) * NCOLS + c4 * 4];
        }
        __syncthreads();
#pragma unroll 8
        for (int k = 0; k < KC; k++) {
            float4 w4 = *(const float4*)&Ws[k][cg * 4];
            u64 w0 = pack2(w4.x, w4.x);
            u64 w1 = pack2(w4.y, w4.y);
            u64 w2 = pack2(w4.z, w4.z);
            u64 w3 = pack2(w4.w, w4.w);
#pragma unroll
            for (int q = 0; q < NP / 2; q++) {
                // 4 consecutive rows = 2 f32x2 pairs, read as one 16B load
                ulonglong2 a2 = *(const ulonglong2*)&As[k][rg * RPT + q * 4];
                acc[q * 2 + 0][0] = fma2(a2.x, w0, acc[q * 2 + 0][0]);
                acc[q * 2 + 0][1] = fma2(a2.x, w1, acc[q * 2 + 0][1]);
                acc[q * 2 + 0][2] = fma2(a2.x, w2, acc[q * 2 + 0][2]);
                acc[q * 2 + 0][3] = fma2(a2.x, w3, acc[q * 2 + 0][3]);
                acc[q * 2 + 1][0] = fma2(a2.y, w0, acc[q * 2 + 1][0]);
                acc[q * 2 + 1][1] = fma2(a2.y, w1, acc[q * 2 + 1][1]);
                acc[q * 2 + 1][2] = fma2(a2.y, w2, acc[q * 2 + 1][2]);
                acc[q * 2 + 1][3] = fma2(a2.y, w3, acc[q * 2 + 1][3]);
            }
        }
        __syncthreads();
    }

    // epilogue: store fp16 C, fused attention dot-products, block/global max
    int col = cg * 4;
    float w_s0 = __ldg(&att_s[col]),     w_s1 = __ldg(&att_s[col + 1]);
    float w_s2 = __ldg(&att_s[col + 2]), w_s3 = __ldg(&att_s[col + 3]);
    float w_d0 = __ldg(&att_d[col]),     w_d1 = __ldg(&att_d[col + 1]);
    float w_d2 = __ldg(&att_d[col + 2]), w_d3 = __ldg(&att_d[col + 3]);

#pragma unroll
    for (int p = 0; p < NP; p++) {
        float2 c0 = unpack2(acc[p][0]);
        float2 c1 = unpack2(acc[p][1]);
        float2 c2 = unpack2(acc[p][2]);
        float2 c3 = unpack2(acc[p][3]);
        float rv[2][4] = {{c0.x, c1.x, c2.x, c3.x},
                          {c0.y, c1.y, c2.y, c3.y}};
#pragma unroll
        for (int s = 0; s < 2; s++) {
            int row = row0 + rg * RPT + 2 * p + s;
            if (row < M) {
                __half2 hlo = __float22half2_rn(make_float2(rv[s][0], rv[s][1]));
                __half2 hhi = __float22half2_rn(make_float2(rv[s][2], rv[s][3]));
                uint2 u;
                u.x = *reinterpret_cast<unsigned*>(&hlo);
                u.y = *reinterpret_cast<unsigned*>(&hhi);
                *(uint2*)&C[(size_t)row * NCOLS + col] = u;
            }
            float ps = rv[s][0] * w_s0 + rv[s][1] * w_s1 + rv[s][2] * w_s2 + rv[s][3] * w_s3;
            float pd = rv[s][0] * w_d0 + rv[s][1] * w_d1 + rv[s][2] * w_d2 + rv[s][3] * w_d3;
#pragma unroll
            for (int off = LPG / 2; off > 0; off >>= 1) {
                ps += __shfl_xor_sync(0xffffffffu, ps, off);
                pd += __shfl_xor_sync(0xffffffffu, pd, off);
            }
            if ((cg % LPG) == 0 && row < M) {
                int h = cg / LPG;
                a_s[row * H + h] = ps;
                a_d[row * H + h] = pd;
                atomicMax(&sm_mx[h], encf(ps));
            }
        }
    }
    __syncthreads();
    if (tid < H) atomicMax(&g_Mu[mu0 + tid], sm_mx[tid]);
}

// ---------------------------------------------------------------------------
// Single-pass softmax aggregation over fp16 features, fp32 accumulate.
// ---------------------------------------------------------------------------

template <int H, int C, int VECH, bool ELU_OUT>
__global__ void agg_kernel(const __half* __restrict__ hin,
                           const float* __restrict__ a_s,
                           const float* __restrict__ a_dv,
                           const float* __restrict__ bias,
                           float* __restrict__ out, int mu0, int N) {
    constexpr int F = H * C;
    int gw   = (blockIdx.x * blockDim.x + threadIdx.x) >> 5;
    int lane = threadIdx.x & 31;
    if (gw >= N) return;

    int   h_own = (lane * VECH) / C;
    float ad    = __ldg(&a_dv[gw * H + h_own]);
    float tM    = decf(g_Mu[mu0 + h_own]) + ad;
    float S     = fmaxf(tM, 0.2f * tM);

    int beg = g_rowptr[gw], end = g_rowptr[gw + 1];
    float d = 0.f;
    float acc[VECH];
#pragma unroll
    for (int q = 0; q < VECH; q++) acc[q] = 0.f;

    for (int base = beg; base < end; base += 32) {
        int idx = base + lane;
        int sl  = (idx < end) ? g_col[idx] : 0;
        int cnt = min(32, end - base);
#pragma unroll 4
        for (int j = 0; j < cnt; j++) {
            int s = __shfl_sync(0xffffffffu, sl, j);
            float e = __ldg(&a_s[s * H + h_own]) + ad;
            e = fmaxf(e, 0.2f * e);
            float ev = __expf(e - S);
            d += ev;
            const __half* hr = hin + (size_t)s * F + lane * VECH;
            if (VECH == 4) {
                uint2 u = __ldg((const uint2*)hr);
                float2 f0 = __half22float2(*reinterpret_cast<__half2*>(&u.x));
                float2 f1 = __half22float2(*reinterpret_cast<__half2*>(&u.y));
                acc[0] = fmaf(ev, f0.x, acc[0]);
                acc[1] = fmaf(ev, f0.y, acc[1]);
                acc[2] = fmaf(ev, f1.x, acc[2]);
                acc[3] = fmaf(ev, f1.y, acc[3]);
            } else {
                unsigned u = __ldg((const unsigned*)hr);
                float2 f0 = __half22float2(*reinterpret_cast<__half2*>(&u));
                acc[0] = fmaf(ev, f0.x, acc[0]);
                acc[1] = fmaf(ev, f0.y, acc[1]);
            }
        }
    }

    float inv = 1.f / d;
#pragma unroll
    for (int q = 0; q < VECH; q++) {
        int f = lane * VECH + q;
        float v = acc[q] * inv + __ldg(&bias[f]);
        if (ELU_OUT) v = (v > 0.f) ? v : (__expf(v) - 1.f);
        out[(size_t)gw * F + f] = v;
    }
}

// ---------------------------------------------------------------------------
// Launch
// ---------------------------------------------------------------------------

extern "C" void kernel_launch(void* const* d_in, const int* in_sizes, int n_in,
                              void* d_out, int out_size) {
    const float* x    = (const float*)d_in[0];
    const int*   ei   = (const int*)d_in[1];   // int32 [2, E]
    const float* W1   = (const float*)d_in[2];
    const float* as1w = (const float*)d_in[3];
    const float* ad1w = (const float*)d_in[4];
    const float* b1   = (const float*)d_in[5];
    const float* W2   = (const float*)d_in[6];
    const float* as2w = (const float*)d_in[7];
    const float* ad2w = (const float*)d_in[8];
    const float* b2   = (const float*)d_in[9];
    float* out = (float*)d_out;

    int N  = in_sizes[0] / 128;
    int E  = in_sizes[1] / 2;

    void *p_h1, *p_h2, *p_out1, *p_as1, *p_ad1, *p_as2, *p_ad2;
    cudaGetSymbolAddress(&p_h1,   g_h1h);
    cudaGetSymbolAddress(&p_h2,   g_h2h);
    cudaGetSymbolAddress(&p_out1, g_out1);
    cudaGetSymbolAddress(&p_as1,  g_as1);
    cudaGetSymbolAddress(&p_ad1,  g_ad1);
    cudaGetSymbolAddress(&p_as2,  g_as2);
    cudaGetSymbolAddress(&p_ad2,  g_ad2);

    int scanSmem = (N + 2048) * (int)sizeof(int);
    cudaFuncSetAttribute(scan_kernel, cudaFuncAttributeMaxDynamicSharedMemorySize, scanSmem);

    int nodeBlocks = (N + 255) / 256;
    int histBlocks = ((E + 3) / 4 + 255) / 256;
    int scatBlocks = ((E + 3) / 4 + N + 255) / 256;
    int warpBlocks = (N + 7) / 8;
    int gemmBlocks = (N + 63) / 64;

    zero_kernel<<<nodeBlocks, 256>>>(N);
    hist_kernel<<<histBlocks, 256>>>(ei, E);
    scan_kernel<<<1, 1024, scanSmem>>>(N);
    scatter_kernel<<<scatBlocks, 256>>>(ei, E, N);

    sgemm_attn_kernel<128, 4><<<gemmBlocks, 256>>>(
        x, W1, (__half*)p_h1, as1w, ad1w, (float*)p_as1, (float*)p_ad1, 0, N);
    agg_kernel<4, 32, 4, true><<<warpBlocks, 256>>>(
        (const __half*)p_h1, (const float*)p_as1, (const float*)p_ad1,
        b1, (float*)p_out1, 0, N);

    sgemm_attn_kernel<64, 1><<<gemmBlocks, 256>>>(
        (const float*)p_out1, W2, (__half*)p_h2, as2w, ad2w,
        (float*)p_as2, (float*)p_ad2, 4, N);
    agg_kernel<1, 64, 2, false><<<warpBlocks, 256>>>(
        (const __half*)p_h2, (const float*)p_as2, (const float*)p_ad2,
        b2, out, 4, N);
}